// round 2
// baseline (speedup 1.0000x reference)
#include <cuda_runtime.h>

// Problem constants (fixed shapes from reference setup_inputs)
#define TLEN 2048
#define BSZ  512
#define HD   64
#define G4   256          // 4*H gates
#define BPB  4            // batch rows per block
#define NTHREADS 512      // 2 threads per gate (K-split halves)
#define NBLOCKS (BSZ / BPB)   // 128

// Shared memory layout (floats)
//   WT0v [256][68]   per-gate column of w_hh0, padded        @ 0      (17408)
//   WT1v [256][132]  per-gate column of [w_ih1 | w_hh1]      @ 17408  (33792)
//   bs0  [256]                                               @ 51200
//   bs1  [256]                                               @ 51456
//   wi0  [256]                                               @ 51712
//   h1s  [4][64]                                             @ 51968
//   h2s  [4][64]                                             @ 52224
//   gp   [2][4][256]  partial gate sums (half, batch, gate)  @ 52480  (2048)
//   ms   [4][128]     fc1 activations                        @ 54528  (512)
#define OFF_WT1 17408
#define OFF_BS0 51200
#define OFF_BS1 51456
#define OFF_WI0 51712
#define OFF_H1  51968
#define OFF_H2  52224
#define OFF_GP  52480
#define OFF_MS  54528
#define SMEM_FLOATS 55040   // 220,160 bytes

#define W0STR 68
#define W1STR 132

typedef unsigned long long u64;

__device__ __forceinline__ u64 ffma2(u64 a, u64 b, u64 c) {
    u64 d;
    asm("fma.rn.f32x2 %0, %1, %2, %3;" : "=l"(d) : "l"(a), "l"(b), "l"(c));
    return d;
}
__device__ __forceinline__ float hsum2(u64 v) {
    float lo, hi;
    asm("mov.b64 {%0, %1}, %2;" : "=f"(lo), "=f"(hi) : "l"(v));
    return lo + hi;
}

__device__ __forceinline__ float sigm_f(float v) {
    return __fdividef(1.0f, 1.0f + __expf(-v));
}
__device__ __forceinline__ float tanh_f(float v) {
    return fmaf(2.0f, __fdividef(1.0f, 1.0f + __expf(-2.0f * v)), -1.0f);
}

// 64-element packed dot-product chunk: acc pairs over 16 K-steps (4 float4 iters)
// wcol: padded weight column base for this thread's K-range
// hb:   h base for batch 0 within this K-range (batches stride HD)
#define DOT16(A0,A1,A2,A3,wcol,hb,k4)                                          \
    {                                                                          \
        const ulonglong2 w2 = *(const ulonglong2*)((wcol) + (k4));             \
        const ulonglong2 p0 = *(const ulonglong2*)((hb) + 0*HD + (k4));        \
        const ulonglong2 p1 = *(const ulonglong2*)((hb) + 1*HD + (k4));        \
        const ulonglong2 p2 = *(const ulonglong2*)((hb) + 2*HD + (k4));        \
        const ulonglong2 p3 = *(const ulonglong2*)((hb) + 3*HD + (k4));        \
        A0 = ffma2(w2.x, p0.x, A0); A0 = ffma2(w2.y, p0.y, A0);                \
        A1 = ffma2(w2.x, p1.x, A1); A1 = ffma2(w2.y, p1.y, A1);                \
        A2 = ffma2(w2.x, p2.x, A2); A2 = ffma2(w2.y, p2.y, A2);                \
        A3 = ffma2(w2.x, p3.x, A3); A3 = ffma2(w2.y, p3.y, A3);                \
    }

__global__ __launch_bounds__(NTHREADS, 1)
void lstm2_persistent_kernel(
    const float* __restrict__ x,      // [B, T]
    const float* __restrict__ w_ih0,  // [256, 1]
    const float* __restrict__ w_hh0,  // [256, 64]
    const float* __restrict__ b_ih0,  // [256]
    const float* __restrict__ b_hh0,  // [256]
    const float* __restrict__ w_ih1,  // [256, 64]
    const float* __restrict__ w_hh1,  // [256, 64]
    const float* __restrict__ b_ih1,  // [256]
    const float* __restrict__ b_hh1,  // [256]
    const float* __restrict__ fc1_w,  // [128, 64]
    const float* __restrict__ fc1_b,  // [128]
    const float* __restrict__ fc2_w,  // [10, 128]
    const float* __restrict__ fc2_b,  // [10]
    float* __restrict__ out)          // [B, 10]
{
    extern __shared__ float sm[];
    float* WT0v = sm;
    float* WT1v = sm + OFF_WT1;
    float* bs0  = sm + OFF_BS0;
    float* bs1  = sm + OFF_BS1;
    float* wi0  = sm + OFF_WI0;
    float* h1s  = sm + OFF_H1;
    float* h2s  = sm + OFF_H2;
    float* gp   = sm + OFF_GP;
    float* ms   = sm + OFF_MS;

    const int tid   = threadIdx.x;
    const int l     = tid & 31;
    const int j     = tid & 255;      // gate index
    const int half  = tid >> 8;       // K-split half (0 or 1)
    const int bbase = blockIdx.x * BPB;

    // ---- Load weights into padded per-gate-column SMEM (vectorized) ----
    // w_hh0[j][d] -> WT0v[j*68 + d]
    for (int i4 = tid; i4 < G4 * (HD / 4); i4 += NTHREADS) {
        int jj = i4 >> 4;
        int d4 = (i4 & 15) << 2;
        float4 v = *(const float4*)&w_hh0[jj * HD + d4];
        *(float4*)&WT0v[jj * W0STR + d4] = v;
    }
    // w_ih1[j][d] -> WT1v[j*132 + d];  w_hh1[j][d] -> WT1v[j*132 + 64 + d]
    for (int i4 = tid; i4 < G4 * (HD / 4); i4 += NTHREADS) {
        int jj = i4 >> 4;
        int d4 = (i4 & 15) << 2;
        float4 v1 = *(const float4*)&w_ih1[jj * HD + d4];
        float4 v2 = *(const float4*)&w_hh1[jj * HD + d4];
        *(float4*)&WT1v[jj * W1STR + d4]      = v1;
        *(float4*)&WT1v[jj * W1STR + 64 + d4] = v2;
    }
    for (int i = tid; i < G4; i += NTHREADS) {
        bs0[i] = b_ih0[i] + b_hh0[i];
        bs1[i] = b_ih1[i] + b_hh1[i];
        wi0[i] = w_ih0[i];
    }
    for (int i = tid; i < BPB * HD; i += NTHREADS) {
        h1s[i] = 0.0f;
        h2s[i] = 0.0f;
    }
    __syncthreads();

    // Per-thread constants
    const float wj0 = wi0[j];
    const float bj0 = bs0[j];
    const float bj1 = bs1[j];

    // Pointwise ownership (threads 0..255): (batch pb, unit pu)
    const int pb = (tid >> 6) & 3;
    const int pu = tid & 63;
    float c1 = 0.0f, c2 = 0.0f;
    // Cache biases for pointwise lanes (only meaningful for tid<256)
    // Not used in GEMV path; biases for layer gates already added at GEMV extract.

    // Weight column bases for this thread
    const float* wc0 = &WT0v[j * W0STR + half * 32];   // 32 K-steps for layer 1
    const float* wc1 = &WT1v[j * W1STR + half * 64];   // 64 K-steps for layer 2
    const float* h2base_l1 = h1s + half * 32;          // layer1 h range
    const float* hbase_l2  = half ? h2s : h1s;         // layer2: half0 -> h1 (w_ih1), half1 -> h2 (w_hh1)

    float* gp0 = gp;          // [4][256]
    float* gp1 = gp + 1024;   // [4][256]
    float* gpw = half ? gp1 : gp0;

    // x prefetch (lanes 0..3 hold batch rows)
    float xcur = 0.0f;
    if (l < BPB) xcur = x[(bbase + l) * TLEN + 0];

    for (int t = 0; t < TLEN; ++t) {
        // broadcast current x, prefetch next
        float xv0 = __shfl_sync(0xffffffffu, xcur, 0);
        float xv1 = __shfl_sync(0xffffffffu, xcur, 1);
        float xv2 = __shfl_sync(0xffffffffu, xcur, 2);
        float xv3 = __shfl_sync(0xffffffffu, xcur, 3);
        if (l < BPB && t + 1 < TLEN) xcur = x[(bbase + l) * TLEN + t + 1];

        // ============ Phase A: layer-1 gate GEMV (K split 32/32) ============
        {
            u64 A0 = 0, A1 = 0, A2 = 0, A3 = 0;
            #pragma unroll
            for (int k4 = 0; k4 < 32; k4 += 4)
                DOT16(A0, A1, A2, A3, wc0, h2base_l1, k4);
            float s0 = hsum2(A0), s1 = hsum2(A1), s2 = hsum2(A2), s3 = hsum2(A3);
            if (half == 0) {
                s0 = fmaf(wj0, xv0, s0 + bj0);
                s1 = fmaf(wj0, xv1, s1 + bj0);
                s2 = fmaf(wj0, xv2, s2 + bj0);
                s3 = fmaf(wj0, xv3, s3 + bj0);
            }
            gpw[0 * G4 + j] = s0;
            gpw[1 * G4 + j] = s1;
            gpw[2 * G4 + j] = s2;
            gpw[3 * G4 + j] = s3;
        }
        __syncthreads();

        // ============ Phase B: layer-1 pointwise (threads 0..255) ============
        if (tid < 256) {
            const float* a = &gp0[pb * G4];
            const float* b = &gp1[pb * G4];
            float gi = a[pu]       + b[pu];
            float gf = a[64 + pu]  + b[64 + pu];
            float gg = a[128 + pu] + b[128 + pu];
            float go = a[192 + pu] + b[192 + pu];
            float iv = sigm_f(gi);
            float fv = sigm_f(gf);
            float gv = tanh_f(gg);
            float ov = sigm_f(go);
            c1 = fmaf(fv, c1, iv * gv);
            h1s[pb * HD + pu] = ov * tanh_f(c1);
        }
        __syncthreads();

        // ============ Phase C: layer-2 gate GEMV (K=128 split 64/64) ============
        {
            u64 A0 = 0, A1 = 0, A2 = 0, A3 = 0;
            #pragma unroll
            for (int k4 = 0; k4 < 64; k4 += 4)
                DOT16(A0, A1, A2, A3, wc1, hbase_l2, k4);
            float s0 = hsum2(A0), s1 = hsum2(A1), s2 = hsum2(A2), s3 = hsum2(A3);
            if (half == 0) { s0 += bj1; s1 += bj1; s2 += bj1; s3 += bj1; }
            gpw[0 * G4 + j] = s0;
            gpw[1 * G4 + j] = s1;
            gpw[2 * G4 + j] = s2;
            gpw[3 * G4 + j] = s3;
        }
        __syncthreads();

        // ============ Phase D: layer-2 pointwise (threads 0..255) ============
        if (tid < 256) {
            const float* a = &gp0[pb * G4];
            const float* b = &gp1[pb * G4];
            float gi = a[pu]       + b[pu];
            float gf = a[64 + pu]  + b[64 + pu];
            float gg = a[128 + pu] + b[128 + pu];
            float go = a[192 + pu] + b[192 + pu];
            float iv = sigm_f(gi);
            float fv = sigm_f(gf);
            float gv = tanh_f(gg);
            float ov = sigm_f(go);
            c2 = fmaf(fv, c2, iv * gv);
            h2s[pb * HD + pu] = ov * tanh_f(c2);
        }
        __syncthreads();
    }

    // ================= Head: y = relu(hT @ fc1.T + b1) @ fc2.T + b2 =================
    // fc1: 4 batches x 128 outs = 512 dots of length 64 (one per thread)
    {
        int b = tid >> 7;
        int n = tid & 127;
        float acc = fc1_b[n];
        const float* wr = &fc1_w[n * HD];
        const float* hr = &h2s[b * HD];
        #pragma unroll
        for (int d = 0; d < HD; ++d) acc = fmaf(wr[d], hr[d], acc);
        ms[tid] = fmaxf(acc, 0.0f);
    }
    __syncthreads();
    // fc2: 4 batches x 10 outs = 40 dots of length 128
    if (tid < BPB * 10) {
        int b = tid / 10;
        int n = tid - b * 10;
        float acc = fc2_b[n];
        const float* wr = &fc2_w[n * 128];
        const float* mr = &ms[b * 128];
        #pragma unroll
        for (int k = 0; k < 128; ++k) acc = fmaf(wr[k], mr[k], acc);
        out[(bbase + b) * 10 + n] = acc;
    }
}

extern "C" void kernel_launch(void* const* d_in, const int* in_sizes, int n_in,
                              void* d_out, int out_size)
{
    const float* x     = (const float*)d_in[0];
    const float* w_ih0 = (const float*)d_in[1];
    const float* w_hh0 = (const float*)d_in[2];
    const float* b_ih0 = (const float*)d_in[3];
    const float* b_hh0 = (const float*)d_in[4];
    const float* w_ih1 = (const float*)d_in[5];
    const float* w_hh1 = (const float*)d_in[6];
    const float* b_ih1 = (const float*)d_in[7];
    const float* b_hh1 = (const float*)d_in[8];
    const float* fc1_w = (const float*)d_in[9];
    const float* fc1_b = (const float*)d_in[10];
    const float* fc2_w = (const float*)d_in[11];
    const float* fc2_b = (const float*)d_in[12];
    float* out = (float*)d_out;

    size_t smem = (size_t)SMEM_FLOATS * sizeof(float);
    cudaFuncSetAttribute(lstm2_persistent_kernel,
                         cudaFuncAttributeMaxDynamicSharedMemorySize, (int)smem);
    lstm2_persistent_kernel<<<NBLOCKS, NTHREADS, smem>>>(
        x, w_ih0, w_hh0, b_ih0, b_hh0,
        w_ih1, w_hh1, b_ih1, b_hh1,
        fc1_w, fc1_b, fc2_w, fc2_b, out);
}

// round 3
// speedup vs baseline: 1.6927x; 1.6927x over previous
#include <cuda_runtime.h>

// Fixed shapes
#define TLEN 2048
#define HD   64
#define G4   256
#define BPB  4
#define NTHREADS 512
#define NBLOCKS  128

// Shared memory (floats): h1s[4*64] | h2s[4*64] | gbuf[4*256] | ms[4*128]
#define OFF_H2  256
#define OFF_GB  512
#define OFF_MS  1536
#define SMEM_TOT 2048   // 8 KB

__device__ __forceinline__ float sigm_f(float v) {
    return __fdividef(1.0f, 1.0f + __expf(-v));
}
__device__ __forceinline__ float tanh_f(float v) {
    return fmaf(2.0f, __fdividef(1.0f, 1.0f + __expf(-2.0f * v)), -1.0f);
}

__global__ __launch_bounds__(NTHREADS, 1)
void lstm2_regw_kernel(
    const float* __restrict__ x,      // [B, T]
    const float* __restrict__ w_ih0,  // [256, 1]
    const float* __restrict__ w_hh0,  // [256, 64]
    const float* __restrict__ b_ih0,  // [256]
    const float* __restrict__ b_hh0,  // [256]
    const float* __restrict__ w_ih1,  // [256, 64]
    const float* __restrict__ w_hh1,  // [256, 64]
    const float* __restrict__ b_ih1,  // [256]
    const float* __restrict__ b_hh1,  // [256]
    const float* __restrict__ fc1_w,  // [128, 64]
    const float* __restrict__ fc1_b,  // [128]
    const float* __restrict__ fc2_w,  // [10, 128]
    const float* __restrict__ fc2_b,  // [10]
    float* __restrict__ out)          // [B, 10]
{
    __shared__ float sm[SMEM_TOT];
    float* h1s  = sm;
    float* h2s  = sm + OFF_H2;
    float* gbuf = sm + OFF_GB;
    float* ms   = sm + OFF_MS;

    const int tid   = threadIdx.x;
    const int l     = tid & 31;
    const int khalf = (l >> 4) & 1;           // K-split half within warp (lane l <-> l^16)
    const int j     = ((tid >> 5) << 4) | (l & 15);   // gate 0..255 (warp owns 16 gates)
    const int bbase = blockIdx.x * BPB;

    // K-rotation so the two lane-halves hit disjoint SMEM bank groups
    const int rotA   = khalf << 4;            // rotate-by-16 within 32
    const int kbaseA = khalf << 5;            // layer-1 K offset (0 or 32)
    const int rotC   = khalf << 4;            // rotate-by-16 within 64

    // ---- Weights into registers (persistent across all 2048 steps) ----
    float wA[32];
    #pragma unroll
    for (int i = 0; i < 32; ++i)
        wA[i] = w_hh0[j * HD + kbaseA + ((i + rotA) & 31)];

    const float* wsrc1 = khalf ? w_hh1 : w_ih1;
    float wC[64];
    #pragma unroll
    for (int i = 0; i < 64; ++i)
        wC[i] = wsrc1[j * HD + ((i + rotC) & 63)];

    const float bj0 = b_ih0[j] + b_hh0[j];
    const float bj1 = b_ih1[j] + b_hh1[j];
    const float wj0 = w_ih0[j];

    for (int i = tid; i < BPB * HD; i += NTHREADS) { h1s[i] = 0.0f; h2s[i] = 0.0f; }
    __syncthreads();

    // Pointwise ownership (threads 0..255)
    const int pb = (tid >> 6) & 3;
    const int pu = tid & 63;
    float c1 = 0.0f, c2 = 0.0f;

    const float* pA = h1s;                    // layer-1 h source (offset added per k)
    const float* pC = khalf ? h2s : h1s;      // layer-2 h source per half

    float xcur = 0.0f;
    if (l < BPB) xcur = x[(bbase + l) * TLEN + 0];

    for (int t = 0; t < TLEN; ++t) {
        const float xv0 = __shfl_sync(0xffffffffu, xcur, 0);
        const float xv1 = __shfl_sync(0xffffffffu, xcur, 1);
        const float xv2 = __shfl_sync(0xffffffffu, xcur, 2);
        const float xv3 = __shfl_sync(0xffffffffu, xcur, 3);
        if (l < BPB && t + 1 < TLEN) xcur = x[(bbase + l) * TLEN + t + 1];

        // ======== Phase A: layer-1 gate GEMV (K split 32/32 across lane pair) ========
        {
            float a0 = 0.0f, a1 = 0.0f, a2 = 0.0f, a3 = 0.0f;
            #pragma unroll
            for (int k4 = 0; k4 < 32; k4 += 4) {
                const int koff = kbaseA + ((k4 + rotA) & 31);
                const float* hp = pA + koff;
                float4 hv;
                hv = *(const float4*)(hp + 0 * HD);
                a0 = fmaf(wA[k4+0], hv.x, a0); a0 = fmaf(wA[k4+1], hv.y, a0);
                a0 = fmaf(wA[k4+2], hv.z, a0); a0 = fmaf(wA[k4+3], hv.w, a0);
                hv = *(const float4*)(hp + 1 * HD);
                a1 = fmaf(wA[k4+0], hv.x, a1); a1 = fmaf(wA[k4+1], hv.y, a1);
                a1 = fmaf(wA[k4+2], hv.z, a1); a1 = fmaf(wA[k4+3], hv.w, a1);
                hv = *(const float4*)(hp + 2 * HD);
                a2 = fmaf(wA[k4+0], hv.x, a2); a2 = fmaf(wA[k4+1], hv.y, a2);
                a2 = fmaf(wA[k4+2], hv.z, a2); a2 = fmaf(wA[k4+3], hv.w, a2);
                hv = *(const float4*)(hp + 3 * HD);
                a3 = fmaf(wA[k4+0], hv.x, a3); a3 = fmaf(wA[k4+1], hv.y, a3);
                a3 = fmaf(wA[k4+2], hv.z, a3); a3 = fmaf(wA[k4+3], hv.w, a3);
            }
            if (khalf == 0) {   // bias + x contribution added once (propagates via xor)
                a0 = fmaf(wj0, xv0, a0 + bj0);
                a1 = fmaf(wj0, xv1, a1 + bj0);
                a2 = fmaf(wj0, xv2, a2 + bj0);
                a3 = fmaf(wj0, xv3, a3 + bj0);
            }
            a0 += __shfl_xor_sync(0xffffffffu, a0, 16);
            a1 += __shfl_xor_sync(0xffffffffu, a1, 16);
            a2 += __shfl_xor_sync(0xffffffffu, a2, 16);
            a3 += __shfl_xor_sync(0xffffffffu, a3, 16);
            if (khalf == 0) { gbuf[0 * G4 + j] = a0; gbuf[1 * G4 + j] = a1; }
            else            { gbuf[2 * G4 + j] = a2; gbuf[3 * G4 + j] = a3; }
        }
        __syncthreads();

        // ======== Phase B: layer-1 pointwise ========
        if (tid < 256) {
            const float* gb = gbuf + pb * G4;
            float iv = sigm_f(gb[pu]);
            float fv = sigm_f(gb[64 + pu]);
            float gv = tanh_f(gb[128 + pu]);
            float ov = sigm_f(gb[192 + pu]);
            c1 = fmaf(fv, c1, iv * gv);
            h1s[pb * HD + pu] = ov * tanh_f(c1);
        }
        __syncthreads();

        // ======== Phase C: layer-2 gate GEMV (khalf0: w_ih1·h1, khalf1: w_hh1·h2) ========
        {
            float a0 = 0.0f, a1 = 0.0f, a2 = 0.0f, a3 = 0.0f;
            #pragma unroll
            for (int k4 = 0; k4 < 64; k4 += 4) {
                const int koff = (k4 + rotC) & 63;
                const float* hp = pC + koff;
                float4 hv;
                hv = *(const float4*)(hp + 0 * HD);
                a0 = fmaf(wC[k4+0], hv.x, a0); a0 = fmaf(wC[k4+1], hv.y, a0);
                a0 = fmaf(wC[k4+2], hv.z, a0); a0 = fmaf(wC[k4+3], hv.w, a0);
                hv = *(const float4*)(hp + 1 * HD);
                a1 = fmaf(wC[k4+0], hv.x, a1); a1 = fmaf(wC[k4+1], hv.y, a1);
                a1 = fmaf(wC[k4+2], hv.z, a1); a1 = fmaf(wC[k4+3], hv.w, a1);
                hv = *(const float4*)(hp + 2 * HD);
                a2 = fmaf(wC[k4+0], hv.x, a2); a2 = fmaf(wC[k4+1], hv.y, a2);
                a2 = fmaf(wC[k4+2], hv.z, a2); a2 = fmaf(wC[k4+3], hv.w, a2);
                hv = *(const float4*)(hp + 3 * HD);
                a3 = fmaf(wC[k4+0], hv.x, a3); a3 = fmaf(wC[k4+1], hv.y, a3);
                a3 = fmaf(wC[k4+2], hv.z, a3); a3 = fmaf(wC[k4+3], hv.w, a3);
            }
            if (khalf == 0) { a0 += bj1; a1 += bj1; a2 += bj1; a3 += bj1; }
            a0 += __shfl_xor_sync(0xffffffffu, a0, 16);
            a1 += __shfl_xor_sync(0xffffffffu, a1, 16);
            a2 += __shfl_xor_sync(0xffffffffu, a2, 16);
            a3 += __shfl_xor_sync(0xffffffffu, a3, 16);
            if (khalf == 0) { gbuf[0 * G4 + j] = a0; gbuf[1 * G4 + j] = a1; }
            else            { gbuf[2 * G4 + j] = a2; gbuf[3 * G4 + j] = a3; }
        }
        __syncthreads();

        // ======== Phase D: layer-2 pointwise ========
        if (tid < 256) {
            const float* gb = gbuf + pb * G4;
            float iv = sigm_f(gb[pu]);
            float fv = sigm_f(gb[64 + pu]);
            float gv = tanh_f(gb[128 + pu]);
            float ov = sigm_f(gb[192 + pu]);
            c2 = fmaf(fv, c2, iv * gv);
            h2s[pb * HD + pu] = ov * tanh_f(c2);
        }
        __syncthreads();
    }

    // ================= Head =================
    {   // fc1: one (batch, out) per thread — 4*128 = 512
        int b = tid >> 7;
        int n = tid & 127;
        float acc = fc1_b[n];
        const float* wr = &fc1_w[n * HD];
        const float* hr = &h2s[b * HD];
        #pragma unroll
        for (int d = 0; d < HD; ++d) acc = fmaf(wr[d], hr[d], acc);
        ms[tid] = fmaxf(acc, 0.0f);
    }
    __syncthreads();
    if (tid < BPB * 10) {
        int b = tid / 10;
        int n = tid - b * 10;
        float acc = fc2_b[n];
        const float* wr = &fc2_w[n * 128];
        const float* mr = &ms[b * 128];
        #pragma unroll
        for (int k = 0; k < 128; ++k) acc = fmaf(wr[k], mr[k], acc);
        out[(bbase + b) * 10 + n] = acc;
    }
}

extern "C" void kernel_launch(void* const* d_in, const int* in_sizes, int n_in,
                              void* d_out, int out_size)
{
    const float* x     = (const float*)d_in[0];
    const float* w_ih0 = (const float*)d_in[1];
    const float* w_hh0 = (const float*)d_in[2];
    const float* b_ih0 = (const float*)d_in[3];
    const float* b_hh0 = (const float*)d_in[4];
    const float* w_ih1 = (const float*)d_in[5];
    const float* w_hh1 = (const float*)d_in[6];
    const float* b_ih1 = (const float*)d_in[7];
    const float* b_hh1 = (const float*)d_in[8];
    const float* fc1_w = (const float*)d_in[9];
    const float* fc1_b = (const float*)d_in[10];
    const float* fc2_w = (const float*)d_in[11];
    const float* fc2_b = (const float*)d_in[12];
    float* out = (float*)d_out;

    lstm2_regw_kernel<<<NBLOCKS, NTHREADS>>>(
        x, w_ih0, w_hh0, b_ih0, b_hh0,
        w_ih1, w_hh1, b_ih1, b_hh1,
        fc1_w, fc1_b, fc2_w, fc2_b, out);
}

// round 4
// speedup vs baseline: 1.7477x; 1.0325x over previous
#include <cuda_runtime.h>

// Fixed shapes
#define TLEN 2048
#define HD   64
#define G4   256
#define BPB  4
#define NTHREADS 512
#define NBLOCKS  128

// Shared memory (floats): h1s[4*64] | h2s[4*64] | g1[4*256] | g2[4*256] | ms[4*128]
#define OFF_H2  256
#define OFF_G1  512
#define OFF_G2  1536
#define OFF_MS  2560
#define SMEM_TOT 3072   // 12 KB

__device__ __forceinline__ float sigm_f(float v) {
    return __fdividef(1.0f, 1.0f + __expf(-v));
}
__device__ __forceinline__ float tanh_f(float v) {
    return fmaf(2.0f, __fdividef(1.0f, 1.0f + __expf(-2.0f * v)), -1.0f);
}

// 4-batch FMA block: weights wreg[4i..4i+3] times h[b][koff..koff+3]
#define GEMV4(AX0,AX1,AX2,AX3,wreg,i,hbase,cstoff)                              \
    {                                                                           \
        float4 hv;                                                              \
        hv = *(const float4*)((hbase) + 0 * HD + (cstoff));                     \
        AX0 = fmaf((wreg)[4*(i)+0], hv.x, AX0); AX0 = fmaf((wreg)[4*(i)+1], hv.y, AX0); \
        AX0 = fmaf((wreg)[4*(i)+2], hv.z, AX0); AX0 = fmaf((wreg)[4*(i)+3], hv.w, AX0); \
        hv = *(const float4*)((hbase) + 1 * HD + (cstoff));                     \
        AX1 = fmaf((wreg)[4*(i)+0], hv.x, AX1); AX1 = fmaf((wreg)[4*(i)+1], hv.y, AX1); \
        AX1 = fmaf((wreg)[4*(i)+2], hv.z, AX1); AX1 = fmaf((wreg)[4*(i)+3], hv.w, AX1); \
        hv = *(const float4*)((hbase) + 2 * HD + (cstoff));                     \
        AX2 = fmaf((wreg)[4*(i)+0], hv.x, AX2); AX2 = fmaf((wreg)[4*(i)+1], hv.y, AX2); \
        AX2 = fmaf((wreg)[4*(i)+2], hv.z, AX2); AX2 = fmaf((wreg)[4*(i)+3], hv.w, AX2); \
        hv = *(const float4*)((hbase) + 3 * HD + (cstoff));                     \
        AX3 = fmaf((wreg)[4*(i)+0], hv.x, AX3); AX3 = fmaf((wreg)[4*(i)+1], hv.y, AX3); \
        AX3 = fmaf((wreg)[4*(i)+2], hv.z, AX3); AX3 = fmaf((wreg)[4*(i)+3], hv.w, AX3); \
    }

__global__ __launch_bounds__(NTHREADS, 1)
void lstm2_pipe_kernel(
    const float* __restrict__ x,      // [B, T]
    const float* __restrict__ w_ih0,  // [256, 1]
    const float* __restrict__ w_hh0,  // [256, 64]
    const float* __restrict__ b_ih0,  // [256]
    const float* __restrict__ b_hh0,  // [256]
    const float* __restrict__ w_ih1,  // [256, 64]
    const float* __restrict__ w_hh1,  // [256, 64]
    const float* __restrict__ b_ih1,  // [256]
    const float* __restrict__ b_hh1,  // [256]
    const float* __restrict__ fc1_w,  // [128, 64]
    const float* __restrict__ fc1_b,  // [128]
    const float* __restrict__ fc2_w,  // [10, 128]
    const float* __restrict__ fc2_b,  // [10]
    float* __restrict__ out)          // [B, 10]
{
    __shared__ float sm[SMEM_TOT];
    float* h1s = sm;
    float* h2s = sm + OFF_H2;
    float* g1  = sm + OFF_G1;
    float* g2  = sm + OFF_G2;
    float* ms  = sm + OFF_MS;

    const int tid   = threadIdx.x;
    const int l     = tid & 31;
    const int khalf = (l >> 4) & 1;                  // lane pair l <-> l^16
    const int j     = ((tid >> 5) << 4) | (l & 15);  // gate 0..255
    const int bbase = blockIdx.x * BPB;

    // Interleaved K-split: thread's k-list is k(i) = 8*(i>>2) + 4*khalf + (i&3)
    // -> both lane-halves' float4 loads land in the same 32B span of one row.
    float wA[32];
    #pragma unroll
    for (int i = 0; i < 32; ++i) {
        int k = ((i >> 2) << 3) + (khalf << 2) + (i & 3);
        wA[i] = w_hh0[j * HD + k];
    }
    float wC[64];
    #pragma unroll
    for (int i = 0; i < 32; ++i) {
        int k = ((i >> 2) << 3) + (khalf << 2) + (i & 3);
        wC[i]      = w_ih1[j * HD + k];
        wC[32 + i] = w_hh1[j * HD + k];
    }

    const float bj0 = b_ih0[j] + b_hh0[j];
    const float bj1 = b_ih1[j] + b_hh1[j];
    const float wj0 = w_ih0[j];

    for (int i = tid; i < BPB * HD; i += NTHREADS) { h1s[i] = 0.0f; h2s[i] = 0.0f; }
    __syncthreads();

    // Pointwise ownership: threads 0..255 -> layer1 (c1), 256..511 -> layer2 (c2)
    const int grp = tid >> 8;
    const int pb  = (tid >> 6) & 3;
    const int pu  = tid & 63;
    float cst = 0.0f;
    float* gsel = grp ? g2 : g1;
    float* hsel = grp ? h2s : h1s;

    // Uniform h bases for this thread's interleave slot
    const float* h1p = h1s + (khalf << 2);
    const float* h2p = h2s + (khalf << 2);

    float xcur = 0.0f;
    if (l < BPB) xcur = x[(bbase + l) * TLEN + 0];

    // Pipelined loop: iteration t computes L1 gates(t) and L2 gates(t-1)
    for (int t = 0; t <= TLEN; ++t) {
        const bool doL1 = (t < TLEN);
        const bool doL2 = (t > 0);

        const float xv0 = __shfl_sync(0xffffffffu, xcur, 0);
        const float xv1 = __shfl_sync(0xffffffffu, xcur, 1);
        const float xv2 = __shfl_sync(0xffffffffu, xcur, 2);
        const float xv3 = __shfl_sync(0xffffffffu, xcur, 3);
        if (l < BPB && t + 1 < TLEN) xcur = x[(bbase + l) * TLEN + t + 1];

        // ================= Phase 1: GEMVs =================
        if (doL1) {
            float a0 = 0.0f, a1 = 0.0f, a2 = 0.0f, a3 = 0.0f;
            #pragma unroll
            for (int it = 0; it < 8; ++it)
                GEMV4(a0, a1, a2, a3, wA, it, h1p, it << 3);
            if (khalf == 0) {
                a0 = fmaf(wj0, xv0, a0 + bj0);
                a1 = fmaf(wj0, xv1, a1 + bj0);
                a2 = fmaf(wj0, xv2, a2 + bj0);
                a3 = fmaf(wj0, xv3, a3 + bj0);
            }
            a0 += __shfl_xor_sync(0xffffffffu, a0, 16);
            a1 += __shfl_xor_sync(0xffffffffu, a1, 16);
            a2 += __shfl_xor_sync(0xffffffffu, a2, 16);
            a3 += __shfl_xor_sync(0xffffffffu, a3, 16);
            if (khalf == 0) { g1[0 * G4 + j] = a0; g1[1 * G4 + j] = a1; }
            else            { g1[2 * G4 + j] = a2; g1[3 * G4 + j] = a3; }
        }
        if (doL2) {
            float a0 = 0.0f, a1 = 0.0f, a2 = 0.0f, a3 = 0.0f;
            #pragma unroll
            for (int it = 0; it < 8; ++it)
                GEMV4(a0, a1, a2, a3, wC, it, h1p, it << 3);
            #pragma unroll
            for (int it = 0; it < 8; ++it)
                GEMV4(a0, a1, a2, a3, wC, 8 + it, h2p, it << 3);
            if (khalf == 0) { a0 += bj1; a1 += bj1; a2 += bj1; a3 += bj1; }
            a0 += __shfl_xor_sync(0xffffffffu, a0, 16);
            a1 += __shfl_xor_sync(0xffffffffu, a1, 16);
            a2 += __shfl_xor_sync(0xffffffffu, a2, 16);
            a3 += __shfl_xor_sync(0xffffffffu, a3, 16);
            if (khalf == 0) { g2[0 * G4 + j] = a0; g2[1 * G4 + j] = a1; }
            else            { g2[2 * G4 + j] = a2; g2[3 * G4 + j] = a3; }
        }
        __syncthreads();

        // ================= Phase 2: pointwise (both layers in parallel) =================
        if (grp ? doL2 : doL1) {
            const float* gb = gsel + pb * G4;
            float iv = sigm_f(gb[pu]);
            float fv = sigm_f(gb[64 + pu]);
            float gv = tanh_f(gb[128 + pu]);
            float ov = sigm_f(gb[192 + pu]);
            cst = fmaf(fv, cst, iv * gv);
            hsel[pb * HD + pu] = ov * tanh_f(cst);
        }
        __syncthreads();
    }

    // ================= Head =================
    {   // fc1: one (batch, out) per thread — 4*128 = 512
        int b = tid >> 7;
        int n = tid & 127;
        float acc = fc1_b[n];
        const float* wr = &fc1_w[n * HD];
        const float* hr = &h2s[b * HD];
        #pragma unroll
        for (int d = 0; d < HD; ++d) acc = fmaf(wr[d], hr[d], acc);
        ms[tid] = fmaxf(acc, 0.0f);
    }
    __syncthreads();
    if (tid < BPB * 10) {
        int b = tid / 10;
        int n = tid - b * 10;
        float acc = fc2_b[n];
        const float* wr = &fc2_w[n * 128];
        const float* mr = &ms[b * 128];
        #pragma unroll
        for (int k = 0; k < 128; ++k) acc = fmaf(wr[k], mr[k], acc);
        out[(bbase + b) * 10 + n] = acc;
    }
}

extern "C" void kernel_launch(void* const* d_in, const int* in_sizes, int n_in,
                              void* d_out, int out_size)
{
    const float* x     = (const float*)d_in[0];
    const float* w_ih0 = (const float*)d_in[1];
    const float* w_hh0 = (const float*)d_in[2];
    const float* b_ih0 = (const float*)d_in[3];
    const float* b_hh0 = (const float*)d_in[4];
    const float* w_ih1 = (const float*)d_in[5];
    const float* w_hh1 = (const float*)d_in[6];
    const float* b_ih1 = (const float*)d_in[7];
    const float* b_hh1 = (const float*)d_in[8];
    const float* fc1_w = (const float*)d_in[9];
    const float* fc1_b = (const float*)d_in[10];
    const float* fc2_w = (const float*)d_in[11];
    const float* fc2_b = (const float*)d_in[12];
    float* out = (float*)d_out;

    lstm2_pipe_kernel<<<NBLOCKS, NTHREADS>>>(
        x, w_ih0, w_hh0, b_ih0, b_hh0,
        w_ih1, w_hh1, b_ih1, b_hh1,
        fc1_w, fc1_b, fc2_w, fc2_b, out);
}

// round 5
// speedup vs baseline: 2.1726x; 1.2431x over previous
#include <cuda_runtime.h>

// Fixed shapes
#define TLEN 2048
#define HD   64
#define G4   256
#define BPB  4
#define NTHREADS 512
#define NBLOCKS  128

// Shared memory (floats): h1s[4*64] | h2s[4*64] | g1[4*256] | g2[4*256] | ms[4*128]
#define OFF_H2  256
#define OFF_G1  512
#define OFF_G2  1536
#define OFF_MS  2560
#define SMEM_TOT 3072   // 12 KB

__device__ __forceinline__ float sigm_f(float v) {
    return __fdividef(1.0f, 1.0f + __expf(-v));
}
__device__ __forceinline__ float tanh_f(float v) {
    return fmaf(2.0f, __fdividef(1.0f, 1.0f + __expf(-2.0f * v)), -1.0f);
}

__global__ __launch_bounds__(NTHREADS, 1)
void lstm2_fuse_kernel(
    const float* __restrict__ x,      // [B, T]
    const float* __restrict__ w_ih0,  // [256, 1]
    const float* __restrict__ w_hh0,  // [256, 64]
    const float* __restrict__ b_ih0,  // [256]
    const float* __restrict__ b_hh0,  // [256]
    const float* __restrict__ w_ih1,  // [256, 64]
    const float* __restrict__ w_hh1,  // [256, 64]
    const float* __restrict__ b_ih1,  // [256]
    const float* __restrict__ b_hh1,  // [256]
    const float* __restrict__ fc1_w,  // [128, 64]
    const float* __restrict__ fc1_b,  // [128]
    const float* __restrict__ fc2_w,  // [10, 128]
    const float* __restrict__ fc2_b,  // [10]
    float* __restrict__ out)          // [B, 10]
{
    __shared__ float sm[SMEM_TOT];
    float* h1s = sm;
    float* h2s = sm + OFF_H2;
    float* g1  = sm + OFF_G1;
    float* g2  = sm + OFF_G2;
    float* ms  = sm + OFF_MS;

    const int tid   = threadIdx.x;
    const int l     = tid & 31;
    const int khalf = (l >> 4) & 1;                  // lane pair l <-> l^16
    const int j     = ((tid >> 5) << 4) | (l & 15);  // gate 0..255
    const int bbase = blockIdx.x * BPB;

    // Interleaved K-split: thread's k-list is k(i) = 8*(i>>2) + 4*khalf + (i&3)
    float wA[32];
    #pragma unroll
    for (int i = 0; i < 32; ++i) {
        int k = ((i >> 2) << 3) + (khalf << 2) + (i & 3);
        wA[i] = w_hh0[j * HD + k];
    }
    float wC[64];
    #pragma unroll
    for (int i = 0; i < 32; ++i) {
        int k = ((i >> 2) << 3) + (khalf << 2) + (i & 3);
        wC[i]      = w_ih1[j * HD + k];   // applied to h1 (shared loads with wA)
        wC[32 + i] = w_hh1[j * HD + k];   // applied to h2
    }

    const float bj0 = b_ih0[j] + b_hh0[j];
    const float bj1 = b_ih1[j] + b_hh1[j];
    const float wj0 = w_ih0[j];

    for (int i = tid; i < BPB * HD; i += NTHREADS) { h1s[i] = 0.0f; h2s[i] = 0.0f; }
    __syncthreads();

    // Pointwise ownership: threads 0..255 -> layer1 (c1), 256..511 -> layer2 (c2)
    const int grp = tid >> 8;
    const int pb  = (tid >> 6) & 3;
    const int pu  = tid & 63;
    float cst = 0.0f;
    float* gsel = grp ? g2 : g1;
    float* hsel = grp ? h2s : h1s;

    const float* h1p = h1s + (khalf << 2);
    const float* h2p = h2s + (khalf << 2);

    float xcur = 0.0f;
    if (l < BPB) xcur = x[(bbase + l) * TLEN + 0];

    // Pipelined: iteration t computes L1 gates(t) and L2 gates(t-1).
    // Both consume h1(t-1) => single pass over h1s feeds both weight sets.
    for (int t = 0; t <= TLEN; ++t) {
        const float xv0 = __shfl_sync(0xffffffffu, xcur, 0);
        const float xv1 = __shfl_sync(0xffffffffu, xcur, 1);
        const float xv2 = __shfl_sync(0xffffffffu, xcur, 2);
        const float xv3 = __shfl_sync(0xffffffffu, xcur, 3);
        if (l < BPB && t + 1 < TLEN) xcur = x[(bbase + l) * TLEN + t + 1];

        // ===== Phase 1: fused GEMVs (unconditional; unused results discarded) =====
        {
            float a0 = 0.f, a1 = 0.f, a2 = 0.f, a3 = 0.f;   // L1 gates
            float e0 = 0.f, e1 = 0.f, e2 = 0.f, e3 = 0.f;   // L2 gates
            #pragma unroll
            for (int it = 0; it < 8; ++it) {
                const int o = it << 3;
                float4 hv0 = *(const float4*)(h1p + 0 * HD + o);
                float4 hv1 = *(const float4*)(h1p + 1 * HD + o);
                float4 hv2 = *(const float4*)(h1p + 2 * HD + o);
                float4 hv3 = *(const float4*)(h1p + 3 * HD + o);
                const float w0 = wA[4*it+0], w1 = wA[4*it+1], w2 = wA[4*it+2], w3 = wA[4*it+3];
                a0 = fmaf(w0, hv0.x, a0); a0 = fmaf(w1, hv0.y, a0);
                a0 = fmaf(w2, hv0.z, a0); a0 = fmaf(w3, hv0.w, a0);
                a1 = fmaf(w0, hv1.x, a1); a1 = fmaf(w1, hv1.y, a1);
                a1 = fmaf(w2, hv1.z, a1); a1 = fmaf(w3, hv1.w, a1);
                a2 = fmaf(w0, hv2.x, a2); a2 = fmaf(w1, hv2.y, a2);
                a2 = fmaf(w2, hv2.z, a2); a2 = fmaf(w3, hv2.w, a2);
                a3 = fmaf(w0, hv3.x, a3); a3 = fmaf(w1, hv3.y, a3);
                a3 = fmaf(w2, hv3.z, a3); a3 = fmaf(w3, hv3.w, a3);
                const float v0 = wC[4*it+0], v1 = wC[4*it+1], v2 = wC[4*it+2], v3 = wC[4*it+3];
                e0 = fmaf(v0, hv0.x, e0); e0 = fmaf(v1, hv0.y, e0);
                e0 = fmaf(v2, hv0.z, e0); e0 = fmaf(v3, hv0.w, e0);
                e1 = fmaf(v0, hv1.x, e1); e1 = fmaf(v1, hv1.y, e1);
                e1 = fmaf(v2, hv1.z, e1); e1 = fmaf(v3, hv1.w, e1);
                e2 = fmaf(v0, hv2.x, e2); e2 = fmaf(v1, hv2.y, e2);
                e2 = fmaf(v2, hv2.z, e2); e2 = fmaf(v3, hv2.w, e2);
                e3 = fmaf(v0, hv3.x, e3); e3 = fmaf(v1, hv3.y, e3);
                e3 = fmaf(v2, hv3.z, e3); e3 = fmaf(v3, hv3.w, e3);
            }
            #pragma unroll
            for (int it = 0; it < 8; ++it) {
                const int o = it << 3;
                float4 hv0 = *(const float4*)(h2p + 0 * HD + o);
                float4 hv1 = *(const float4*)(h2p + 1 * HD + o);
                float4 hv2 = *(const float4*)(h2p + 2 * HD + o);
                float4 hv3 = *(const float4*)(h2p + 3 * HD + o);
                const float v0 = wC[32+4*it+0], v1 = wC[32+4*it+1],
                            v2 = wC[32+4*it+2], v3 = wC[32+4*it+3];
                e0 = fmaf(v0, hv0.x, e0); e0 = fmaf(v1, hv0.y, e0);
                e0 = fmaf(v2, hv0.z, e0); e0 = fmaf(v3, hv0.w, e0);
                e1 = fmaf(v0, hv1.x, e1); e1 = fmaf(v1, hv1.y, e1);
                e1 = fmaf(v2, hv1.z, e1); e1 = fmaf(v3, hv1.w, e1);
                e2 = fmaf(v0, hv2.x, e2); e2 = fmaf(v1, hv2.y, e2);
                e2 = fmaf(v2, hv2.z, e2); e2 = fmaf(v3, hv2.w, e2);
                e3 = fmaf(v0, hv3.x, e3); e3 = fmaf(v1, hv3.y, e3);
                e3 = fmaf(v2, hv3.z, e3); e3 = fmaf(v3, hv3.w, e3);
            }
            if (khalf == 0) {
                a0 = fmaf(wj0, xv0, a0 + bj0);
                a1 = fmaf(wj0, xv1, a1 + bj0);
                a2 = fmaf(wj0, xv2, a2 + bj0);
                a3 = fmaf(wj0, xv3, a3 + bj0);
                e0 += bj1; e1 += bj1; e2 += bj1; e3 += bj1;
            }
            a0 += __shfl_xor_sync(0xffffffffu, a0, 16);
            a1 += __shfl_xor_sync(0xffffffffu, a1, 16);
            a2 += __shfl_xor_sync(0xffffffffu, a2, 16);
            a3 += __shfl_xor_sync(0xffffffffu, a3, 16);
            e0 += __shfl_xor_sync(0xffffffffu, e0, 16);
            e1 += __shfl_xor_sync(0xffffffffu, e1, 16);
            e2 += __shfl_xor_sync(0xffffffffu, e2, 16);
            e3 += __shfl_xor_sync(0xffffffffu, e3, 16);
            if (khalf == 0) {
                g1[0 * G4 + j] = a0; g1[1 * G4 + j] = a1;
                g2[0 * G4 + j] = e0; g2[1 * G4 + j] = e1;
            } else {
                g1[2 * G4 + j] = a2; g1[3 * G4 + j] = a3;
                g2[2 * G4 + j] = e2; g2[3 * G4 + j] = e3;
            }
        }
        __syncthreads();

        // ===== Phase 2: pointwise (both layers in parallel) =====
        if (grp ? (t > 0) : (t < TLEN)) {
            const float* gb = gsel + pb * G4;
            float iv = sigm_f(gb[pu]);
            float fv = sigm_f(gb[64 + pu]);
            float gv = tanh_f(gb[128 + pu]);
            float ov = sigm_f(gb[192 + pu]);
            cst = fmaf(fv, cst, iv * gv);
            hsel[pb * HD + pu] = ov * tanh_f(cst);
        }
        __syncthreads();
    }

    // ================= Head =================
    {   // fc1: one (batch, out) per thread — 4*128 = 512
        int b = tid >> 7;
        int n = tid & 127;
        float acc = fc1_b[n];
        const float* wr = &fc1_w[n * HD];
        const float* hr = &h2s[b * HD];
        #pragma unroll
        for (int d = 0; d < HD; ++d) acc = fmaf(wr[d], hr[d], acc);
        ms[tid] = fmaxf(acc, 0.0f);
    }
    __syncthreads();
    if (tid < BPB * 10) {
        int b = tid / 10;
        int n = tid - b * 10;
        float acc = fc2_b[n];
        const float* wr = &fc2_w[n * 128];
        const float* mr = &ms[b * 128];
        #pragma unroll
        for (int k = 0; k < 128; ++k) acc = fmaf(wr[k], mr[k], acc);
        out[(bbase + b) * 10 + n] = acc;
    }
}

extern "C" void kernel_launch(void* const* d_in, const int* in_sizes, int n_in,
                              void* d_out, int out_size)
{
    const float* x     = (const float*)d_in[0];
    const float* w_ih0 = (const float*)d_in[1];
    const float* w_hh0 = (const float*)d_in[2];
    const float* b_ih0 = (const float*)d_in[3];
    const float* b_hh0 = (const float*)d_in[4];
    const float* w_ih1 = (const float*)d_in[5];
    const float* w_hh1 = (const float*)d_in[6];
    const float* b_ih1 = (const float*)d_in[7];
    const float* b_hh1 = (const float*)d_in[8];
    const float* fc1_w = (const float*)d_in[9];
    const float* fc1_b = (const float*)d_in[10];
    const float* fc2_w = (const float*)d_in[11];
    const float* fc2_b = (const float*)d_in[12];
    float* out = (float*)d_out;

    lstm2_fuse_kernel<<<NBLOCKS, NTHREADS>>>(
        x, w_ih0, w_hh0, b_ih0, b_hh0,
        w_ih1, w_hh1, b_ih1, b_hh1,
        fc1_w, fc1_b, fc2_w, fc2_b, out);
}

// round 6
// speedup vs baseline: 2.2543x; 1.0376x over previous
#include <cuda_runtime.h>

// Fixed shapes
#define TLEN 2048
#define HD   64
#define G4   256
#define G4P  264        // padded gate-row stride (bank-conflict-free stores)
#define BPB  4
#define NTHREADS 512
#define NBLOCKS  128

// Shared memory (floats): h1s[256] | h2s[256] | g1[4*264] | g2[4*264] | ms[512]
#define OFF_H2  256
#define OFF_G1  512
#define OFF_G2  1568
#define OFF_MS  2624
#define SMEM_TOT 3136

__device__ __forceinline__ float tanh_ap(float v) {
    float r;
    asm("tanh.approx.f32 %0, %1;" : "=f"(r) : "f"(v));
    return r;
}
__device__ __forceinline__ float sigm_ap(float v) {
    return fmaf(0.5f, tanh_ap(0.5f * v), 0.5f);
}
// select arr[q] with compile-time indices (q in 0..3)
__device__ __forceinline__ float sel4(const float* a, int q) {
    float lo = (q & 1) ? a[1] : a[0];
    float hi = (q & 1) ? a[3] : a[2];
    return (q & 2) ? hi : lo;
}

__global__ __launch_bounds__(NTHREADS, 1)
void lstm2_q4_kernel(
    const float* __restrict__ x,      // [B, T]
    const float* __restrict__ w_ih0,  // [256, 1]
    const float* __restrict__ w_hh0,  // [256, 64]
    const float* __restrict__ b_ih0,  // [256]
    const float* __restrict__ b_hh0,  // [256]
    const float* __restrict__ w_ih1,  // [256, 64]
    const float* __restrict__ w_hh1,  // [256, 64]
    const float* __restrict__ b_ih1,  // [256]
    const float* __restrict__ b_hh1,  // [256]
    const float* __restrict__ fc1_w,  // [128, 64]
    const float* __restrict__ fc1_b,  // [128]
    const float* __restrict__ fc2_w,  // [10, 128]
    const float* __restrict__ fc2_b,  // [10]
    float* __restrict__ out)          // [B, 10]
{
    __shared__ float sm[SMEM_TOT];
    float* h1s = sm;
    float* h2s = sm + OFF_H2;
    float* g1  = sm + OFF_G1;
    float* g2  = sm + OFF_G2;
    float* ms  = sm + OFF_MS;

    const int tid = threadIdx.x;
    const int l   = tid & 31;
    const int q   = (l >> 3) & 3;               // K-quarter (xor partners: l^8, l^16)
    const int g8  = l & 7;
    const int w   = tid >> 5;                   // warp 0..15
    const int p   = w * 8 + g8;                 // gate-pair index 0..127
    const int j0  = p;
    const int j1  = p + 128;
    const int bbase = blockIdx.x * BPB;

    // ---- Weights into registers (K interleaved by quarter: k = 16*i + 4*q + e) ----
    float wA[2][16], wCi[2][16], wCh[2][16];
    #pragma unroll
    for (int g = 0; g < 2; ++g) {
        const int jg = p + g * 128;
        #pragma unroll
        for (int i = 0; i < 4; ++i)
            #pragma unroll
            for (int e = 0; e < 4; ++e) {
                const int k = 16 * i + 4 * q + e;
                wA[g][4*i+e]  = w_hh0[jg * HD + k];
                wCi[g][4*i+e] = w_ih1[jg * HD + k];
                wCh[g][4*i+e] = w_hh1[jg * HD + k];
            }
    }
    const float bj00 = b_ih0[j0] + b_hh0[j0];
    const float bj01 = b_ih0[j1] + b_hh0[j1];
    const float bj10 = b_ih1[j0] + b_hh1[j0];
    const float bj11 = b_ih1[j1] + b_hh1[j1];
    const float wj00 = w_ih0[j0];
    const float wj01 = w_ih0[j1];

    for (int i = tid; i < 2 * BPB * HD; i += NTHREADS) sm[i] = 0.0f;  // h1s + h2s
    __syncthreads();

    // Pointwise ownership: threads 0..255 -> layer1, 256..511 -> layer2
    const int grp = tid >> 8;
    const int pb  = (tid >> 6) & 3;
    const int pu  = tid & 63;
    float cst = 0.0f;
    float* gsel = grp ? g2 : g1;
    float* hsel = grp ? h2s : h1s;

    const float* h1p = h1s + (q << 2);
    const float* h2p = h2s + (q << 2);

    float xcur = 0.0f;
    if (l < BPB) xcur = x[(bbase + l) * TLEN + 0];

    for (int t = 0; t <= TLEN; ++t) {
        const float xq = __shfl_sync(0xffffffffu, xcur, q);
        if (l < BPB && t + 1 < TLEN) xcur = x[(bbase + l) * TLEN + t + 1];

        float a[2][4], e2a[2][4];
        #pragma unroll
        for (int g = 0; g < 2; ++g)
            #pragma unroll
            for (int b = 0; b < 4; ++b) { a[g][b] = 0.0f; e2a[g][b] = 0.0f; }

        // ===== GEMVs: batch-pair blocked, quarter-K, 2 gates =====
        #pragma unroll
        for (int bp = 0; bp < 4; bp += 2) {
            #pragma unroll
            for (int i = 0; i < 4; ++i) {
                const int o = i << 4;
                const float4 u0 = *(const float4*)(h1p + (bp    ) * HD + o);
                const float4 u1 = *(const float4*)(h1p + (bp + 1) * HD + o);
                #pragma unroll
                for (int g = 0; g < 2; ++g) {
                    a[g][bp]   = fmaf(wA[g][4*i+0], u0.x, a[g][bp]);
                    a[g][bp]   = fmaf(wA[g][4*i+1], u0.y, a[g][bp]);
                    a[g][bp]   = fmaf(wA[g][4*i+2], u0.z, a[g][bp]);
                    a[g][bp]   = fmaf(wA[g][4*i+3], u0.w, a[g][bp]);
                    a[g][bp+1] = fmaf(wA[g][4*i+0], u1.x, a[g][bp+1]);
                    a[g][bp+1] = fmaf(wA[g][4*i+1], u1.y, a[g][bp+1]);
                    a[g][bp+1] = fmaf(wA[g][4*i+2], u1.z, a[g][bp+1]);
                    a[g][bp+1] = fmaf(wA[g][4*i+3], u1.w, a[g][bp+1]);
                    e2a[g][bp]   = fmaf(wCi[g][4*i+0], u0.x, e2a[g][bp]);
                    e2a[g][bp]   = fmaf(wCi[g][4*i+1], u0.y, e2a[g][bp]);
                    e2a[g][bp]   = fmaf(wCi[g][4*i+2], u0.z, e2a[g][bp]);
                    e2a[g][bp]   = fmaf(wCi[g][4*i+3], u0.w, e2a[g][bp]);
                    e2a[g][bp+1] = fmaf(wCi[g][4*i+0], u1.x, e2a[g][bp+1]);
                    e2a[g][bp+1] = fmaf(wCi[g][4*i+1], u1.y, e2a[g][bp+1]);
                    e2a[g][bp+1] = fmaf(wCi[g][4*i+2], u1.z, e2a[g][bp+1]);
                    e2a[g][bp+1] = fmaf(wCi[g][4*i+3], u1.w, e2a[g][bp+1]);
                }
            }
            #pragma unroll
            for (int i = 0; i < 4; ++i) {
                const int o = i << 4;
                const float4 v0 = *(const float4*)(h2p + (bp    ) * HD + o);
                const float4 v1 = *(const float4*)(h2p + (bp + 1) * HD + o);
                #pragma unroll
                for (int g = 0; g < 2; ++g) {
                    e2a[g][bp]   = fmaf(wCh[g][4*i+0], v0.x, e2a[g][bp]);
                    e2a[g][bp]   = fmaf(wCh[g][4*i+1], v0.y, e2a[g][bp]);
                    e2a[g][bp]   = fmaf(wCh[g][4*i+2], v0.z, e2a[g][bp]);
                    e2a[g][bp]   = fmaf(wCh[g][4*i+3], v0.w, e2a[g][bp]);
                    e2a[g][bp+1] = fmaf(wCh[g][4*i+0], v1.x, e2a[g][bp+1]);
                    e2a[g][bp+1] = fmaf(wCh[g][4*i+1], v1.y, e2a[g][bp+1]);
                    e2a[g][bp+1] = fmaf(wCh[g][4*i+2], v1.z, e2a[g][bp+1]);
                    e2a[g][bp+1] = fmaf(wCh[g][4*i+3], v1.w, e2a[g][bp+1]);
                }
            }
        }

        // ===== Reduce across the 4 K-quarters (lanes l, l^8, l^16, l^24) =====
        #pragma unroll
        for (int g = 0; g < 2; ++g)
            #pragma unroll
            for (int b = 0; b < 4; ++b) {
                a[g][b]   += __shfl_xor_sync(0xffffffffu, a[g][b],   8);
                a[g][b]   += __shfl_xor_sync(0xffffffffu, a[g][b],   16);
                e2a[g][b] += __shfl_xor_sync(0xffffffffu, e2a[g][b], 8);
                e2a[g][b] += __shfl_xor_sync(0xffffffffu, e2a[g][b], 16);
            }

        // ===== Finalize: this lane stores batch q for its 2 gates, both layers =====
        {
            float ga0 = sel4(a[0], q);
            float ga1 = sel4(a[1], q);
            float ge0 = sel4(e2a[0], q);
            float ge1 = sel4(e2a[1], q);
            ga0 = fmaf(wj00, xq, ga0 + bj00);
            ga1 = fmaf(wj01, xq, ga1 + bj01);
            ge0 += bj10;
            ge1 += bj11;
            g1[q * G4P + j0] = ga0;
            g1[q * G4P + j1] = ga1;
            g2[q * G4P + j0] = ge0;
            g2[q * G4P + j1] = ge1;
        }
        __syncthreads();

        // ===== Pointwise (both layers in parallel, tanh.approx) =====
        if (grp ? (t > 0) : (t < TLEN)) {
            const float* gb = gsel + pb * G4P;
            float iv = sigm_ap(gb[pu]);
            float fv = sigm_ap(gb[64 + pu]);
            float gv = tanh_ap(gb[128 + pu]);
            float ov = sigm_ap(gb[192 + pu]);
            cst = fmaf(fv, cst, iv * gv);
            hsel[pb * HD + pu] = ov * tanh_ap(cst);
        }
        __syncthreads();
    }

    // ================= Head =================
    {   // fc1: one (batch, out) per thread — 4*128 = 512
        int b = tid >> 7;
        int n = tid & 127;
        float acc = fc1_b[n];
        const float* wr = &fc1_w[n * HD];
        const float* hr = &h2s[b * HD];
        #pragma unroll
        for (int d = 0; d < HD; ++d) acc = fmaf(wr[d], hr[d], acc);
        ms[tid] = fmaxf(acc, 0.0f);
    }
    __syncthreads();
    if (tid < BPB * 10) {
        int b = tid / 10;
        int n = tid - b * 10;
        float acc = fc2_b[n];
        const float* wr = &fc2_w[n * 128];
        const float* mr = &ms[b * 128];
        #pragma unroll
        for (int k = 0; k < 128; ++k) acc = fmaf(wr[k], mr[k], acc);
        out[(bbase + b) * 10 + n] = acc;
    }
}

extern "C" void kernel_launch(void* const* d_in, const int* in_sizes, int n_in,
                              void* d_out, int out_size)
{
    const float* x     = (const float*)d_in[0];
    const float* w_ih0 = (const float*)d_in[1];
    const float* w_hh0 = (const float*)d_in[2];
    const float* b_ih0 = (const float*)d_in[3];
    const float* b_hh0 = (const float*)d_in[4];
    const float* w_ih1 = (const float*)d_in[5];
    const float* w_hh1 = (const float*)d_in[6];
    const float* b_ih1 = (const float*)d_in[7];
    const float* b_hh1 = (const float*)d_in[8];
    const float* fc1_w = (const float*)d_in[9];
    const float* fc1_b = (const float*)d_in[10];
    const float* fc2_w = (const float*)d_in[11];
    const float* fc2_b = (const float*)d_in[12];
    float* out = (float*)d_out;

    lstm2_q4_kernel<<<NBLOCKS, NTHREADS>>>(
        x, w_ih0, w_hh0, b_ih0, b_hh0,
        w_ih1, w_hh1, b_ih1, b_hh1,
        fc1_w, fc1_b, fc2_w, fc2_b, out);
}

// round 7
// speedup vs baseline: 2.4885x; 1.1039x over previous
#include <cuda_runtime.h>

// Fixed shapes
#define TLEN 2048
#define HD   64
#define HS   68          // padded h-row stride (conflict-free scattered stores)
#define BPB  4
#define NTHREADS 512
#define NBLOCKS  128

// SMEM (floats): ping-pong h buffers + head scratch
//   bufA: h1@0, h2@272   bufB: h1@544, h2@816   ms@1088
#define BUF   544
#define OFF_H2 272
#define OFF_MS 1088
#define SMEM_TOT 1600

__device__ __forceinline__ float tanh_ap(float v) {
    float r;
    asm("tanh.approx.f32 %0, %1;" : "=f"(r) : "f"(v));
    return r;
}
__device__ __forceinline__ float sigm_ap(float v) {
    return fmaf(0.5f, tanh_ap(0.5f * v), 0.5f);
}

__global__ __launch_bounds__(NTHREADS, 1)
void lstm2_inreg_kernel(
    const float* __restrict__ x,      // [B, T]
    const float* __restrict__ w_ih0,  // [256, 1]
    const float* __restrict__ w_hh0,  // [256, 64]
    const float* __restrict__ b_ih0,  // [256]
    const float* __restrict__ b_hh0,  // [256]
    const float* __restrict__ w_ih1,  // [256, 64]
    const float* __restrict__ w_hh1,  // [256, 64]
    const float* __restrict__ b_ih1,  // [256]
    const float* __restrict__ b_hh1,  // [256]
    const float* __restrict__ fc1_w,  // [128, 64]
    const float* __restrict__ fc1_b,  // [128]
    const float* __restrict__ fc2_w,  // [10, 128]
    const float* __restrict__ fc2_b,  // [10]
    float* __restrict__ out)          // [B, 10]
{
    __shared__ float sm[SMEM_TOT];
    float* ms = sm + OFF_MS;

    const int tid = threadIdx.x;
    const int l   = tid & 31;
    const int q   = l >> 3;           // K-quarter AND the batch this lane finalizes
    const int gg  = (l >> 2) & 1;     // 0: gates {u,u+64} + layer-1 pointwise; 1: {u+128,u+192} + layer-2
    const int uu  = l & 3;
    const int w   = tid >> 5;
    const int u   = w * 4 + uu;       // hidden unit 0..63
    const int j0  = u + gg * 128;
    const int j1  = u + 64 + gg * 128;
    const int bbase = blockIdx.x * BPB;

    // ---- Weights into registers (K interleaved: k = 16*i + 4*q + e) ----
    float wA[2][16], wCi[2][16], wCh[2][16];
    #pragma unroll
    for (int g = 0; g < 2; ++g) {
        const int jg = g ? j1 : j0;
        #pragma unroll
        for (int i = 0; i < 4; ++i)
            #pragma unroll
            for (int e = 0; e < 4; ++e) {
                const int k = 16 * i + 4 * q + e;
                wA[g][4*i+e]  = w_hh0[jg * HD + k];
                wCi[g][4*i+e] = w_ih1[jg * HD + k];
                wCh[g][4*i+e] = w_hh1[jg * HD + k];
            }
    }
    const float bA0 = b_ih0[j0] + b_hh0[j0];
    const float bA1 = b_ih0[j1] + b_hh0[j1];
    const float bE0 = b_ih1[j0] + b_hh1[j0];
    const float bE1 = b_ih1[j1] + b_hh1[j1];
    const float wx0 = w_ih0[j0];
    const float wx1 = w_ih0[j1];

    for (int i = tid; i < OFF_MS; i += NTHREADS) sm[i] = 0.0f;
    __syncthreads();

    float cst = 0.0f;     // c1 (gg=0) or c2 (gg=1) for (unit u, batch q)

    float xcur = 0.0f;
    if (l < BPB) xcur = x[(bbase + l) * TLEN + 0];

    // Pipelined: iter t computes L1 gates(t) [h1(t-1), x(t)] and L2 gates(t-1)
    // [h1(t-1), h2(t-2)]. Ping-pong: read buf(t&1), write buf(1-(t&1)).
    for (int t = 0; t <= TLEN; ++t) {
        const float* hr = sm + ((t & 1) ? BUF : 0);
        float*       hw = sm + ((t & 1) ? 0 : BUF);
        const float* h1p = hr + (q << 2);
        const float* h2p = hr + OFF_H2 + (q << 2);

        const float xq = __shfl_sync(0xffffffffu, xcur, q);
        if (l < BPB && t + 1 < TLEN) xcur = x[(bbase + l) * TLEN + t + 1];

        float vA0 = 0.f, vA1 = 0.f, vE0 = 0.f, vE1 = 0.f;

        #pragma unroll
        for (int bp = 0; bp < 4; bp += 2) {
            float A00=0.f,A01=0.f,A10=0.f,A11=0.f;   // L1: gate{0,1} x batch{bp,bp+1}
            float E00=0.f,E01=0.f,E10=0.f,E11=0.f;   // L2
            #pragma unroll
            for (int i = 0; i < 4; ++i) {
                const int o = i << 4;
                const float4 u0 = *(const float4*)(h1p + (bp    ) * HS + o);
                const float4 u1 = *(const float4*)(h1p + (bp + 1) * HS + o);
                A00=fmaf(wA[0][4*i+0],u0.x,A00); A00=fmaf(wA[0][4*i+1],u0.y,A00);
                A00=fmaf(wA[0][4*i+2],u0.z,A00); A00=fmaf(wA[0][4*i+3],u0.w,A00);
                A01=fmaf(wA[0][4*i+0],u1.x,A01); A01=fmaf(wA[0][4*i+1],u1.y,A01);
                A01=fmaf(wA[0][4*i+2],u1.z,A01); A01=fmaf(wA[0][4*i+3],u1.w,A01);
                A10=fmaf(wA[1][4*i+0],u0.x,A10); A10=fmaf(wA[1][4*i+1],u0.y,A10);
                A10=fmaf(wA[1][4*i+2],u0.z,A10); A10=fmaf(wA[1][4*i+3],u0.w,A10);
                A11=fmaf(wA[1][4*i+0],u1.x,A11); A11=fmaf(wA[1][4*i+1],u1.y,A11);
                A11=fmaf(wA[1][4*i+2],u1.z,A11); A11=fmaf(wA[1][4*i+3],u1.w,A11);
                E00=fmaf(wCi[0][4*i+0],u0.x,E00); E00=fmaf(wCi[0][4*i+1],u0.y,E00);
                E00=fmaf(wCi[0][4*i+2],u0.z,E00); E00=fmaf(wCi[0][4*i+3],u0.w,E00);
                E01=fmaf(wCi[0][4*i+0],u1.x,E01); E01=fmaf(wCi[0][4*i+1],u1.y,E01);
                E01=fmaf(wCi[0][4*i+2],u1.z,E01); E01=fmaf(wCi[0][4*i+3],u1.w,E01);
                E10=fmaf(wCi[1][4*i+0],u0.x,E10); E10=fmaf(wCi[1][4*i+1],u0.y,E10);
                E10=fmaf(wCi[1][4*i+2],u0.z,E10); E10=fmaf(wCi[1][4*i+3],u0.w,E10);
                E11=fmaf(wCi[1][4*i+0],u1.x,E11); E11=fmaf(wCi[1][4*i+1],u1.y,E11);
                E11=fmaf(wCi[1][4*i+2],u1.z,E11); E11=fmaf(wCi[1][4*i+3],u1.w,E11);
            }
            #pragma unroll
            for (int i = 0; i < 4; ++i) {
                const int o = i << 4;
                const float4 v0 = *(const float4*)(h2p + (bp    ) * HS + o);
                const float4 v1 = *(const float4*)(h2p + (bp + 1) * HS + o);
                E00=fmaf(wCh[0][4*i+0],v0.x,E00); E00=fmaf(wCh[0][4*i+1],v0.y,E00);
                E00=fmaf(wCh[0][4*i+2],v0.z,E00); E00=fmaf(wCh[0][4*i+3],v0.w,E00);
                E01=fmaf(wCh[0][4*i+0],v1.x,E01); E01=fmaf(wCh[0][4*i+1],v1.y,E01);
                E01=fmaf(wCh[0][4*i+2],v1.z,E01); E01=fmaf(wCh[0][4*i+3],v1.w,E01);
                E10=fmaf(wCh[1][4*i+0],v0.x,E10); E10=fmaf(wCh[1][4*i+1],v0.y,E10);
                E10=fmaf(wCh[1][4*i+2],v0.z,E10); E10=fmaf(wCh[1][4*i+3],v0.w,E10);
                E11=fmaf(wCh[1][4*i+0],v1.x,E11); E11=fmaf(wCh[1][4*i+1],v1.y,E11);
                E11=fmaf(wCh[1][4*i+2],v1.z,E11); E11=fmaf(wCh[1][4*i+3],v1.w,E11);
            }
            // Reduce the 4 K-quarters (lane groups l, l^8, l^16, l^24)
            A00 += __shfl_xor_sync(0xffffffffu, A00, 8);  A00 += __shfl_xor_sync(0xffffffffu, A00, 16);
            A01 += __shfl_xor_sync(0xffffffffu, A01, 8);  A01 += __shfl_xor_sync(0xffffffffu, A01, 16);
            A10 += __shfl_xor_sync(0xffffffffu, A10, 8);  A10 += __shfl_xor_sync(0xffffffffu, A10, 16);
            A11 += __shfl_xor_sync(0xffffffffu, A11, 8);  A11 += __shfl_xor_sync(0xffffffffu, A11, 16);
            E00 += __shfl_xor_sync(0xffffffffu, E00, 8);  E00 += __shfl_xor_sync(0xffffffffu, E00, 16);
            E01 += __shfl_xor_sync(0xffffffffu, E01, 8);  E01 += __shfl_xor_sync(0xffffffffu, E01, 16);
            E10 += __shfl_xor_sync(0xffffffffu, E10, 8);  E10 += __shfl_xor_sync(0xffffffffu, E10, 16);
            E11 += __shfl_xor_sync(0xffffffffu, E11, 8);  E11 += __shfl_xor_sync(0xffffffffu, E11, 16);
            if ((q >> 1) == (bp >> 1)) {
                vA0 = (q & 1) ? A01 : A00;
                vA1 = (q & 1) ? A11 : A10;
                vE0 = (q & 1) ? E01 : E00;
                vE1 = (q & 1) ? E11 : E10;
            }
        }

        // Bias + x for this lane's gates (batch q)
        vA0 = fmaf(wx0, xq, vA0 + bA0);
        vA1 = fmaf(wx1, xq, vA1 + bA1);
        vE0 += bE0;
        vE1 += bE1;

        // Assemble the 4 gates of this lane's layer via pair exchange (l <-> l^4)
        const float t0 = gg ? vA0 : vE0;
        const float t1 = gg ? vA1 : vE1;
        const float r0 = __shfl_xor_sync(0xffffffffu, t0, 4);
        const float r1 = __shfl_xor_sync(0xffffffffu, t1, 4);
        const float gi = gg ? r0 : vA0;
        const float gf = gg ? r1 : vA1;
        const float gG = gg ? vE0 : r0;
        const float gO = gg ? vE1 : r1;

        // In-register pointwise: gg=0 -> layer1 step t ; gg=1 -> layer2 step t-1
        if (gg ? (t > 0) : (t < TLEN)) {
            const float iv = sigm_ap(gi);
            const float fv = sigm_ap(gf);
            const float gv = tanh_ap(gG);
            const float ov = sigm_ap(gO);
            cst = fmaf(fv, cst, iv * gv);
            hw[gg * OFF_H2 + q * HS + u] = ov * tanh_ap(cst);
        }
        __syncthreads();
    }

    // ================= Head =================
    // final h2 = h2(TLEN-1), written at iter TLEN into buf 1-(TLEN&1) = bufB
    const float* h2f = sm + BUF + OFF_H2;
    {   // fc1: one (batch, out) per thread — 4*128 = 512
        int b = tid >> 7;
        int n = tid & 127;
        float acc = fc1_b[n];
        const float* wr = &fc1_w[n * HD];
        const float* hr = h2f + b * HS;
        #pragma unroll
        for (int d = 0; d < HD; ++d) acc = fmaf(wr[d], hr[d], acc);
        ms[tid] = fmaxf(acc, 0.0f);
    }
    __syncthreads();
    if (tid < BPB * 10) {
        int b = tid / 10;
        int n = tid - b * 10;
        float acc = fc2_b[n];
        const float* wr = &fc2_w[n * 128];
        const float* mr = &ms[b * 128];
        #pragma unroll
        for (int k = 0; k < 128; ++k) acc = fmaf(wr[k], mr[k], acc);
        out[(bbase + b) * 10 + n] = acc;
    }
}

extern "C" void kernel_launch(void* const* d_in, const int* in_sizes, int n_in,
                              void* d_out, int out_size)
{
    const float* x     = (const float*)d_in[0];
    const float* w_ih0 = (const float*)d_in[1];
    const float* w_hh0 = (const float*)d_in[2];
    const float* b_ih0 = (const float*)d_in[3];
    const float* b_hh0 = (const float*)d_in[4];
    const float* w_ih1 = (const float*)d_in[5];
    const float* w_hh1 = (const float*)d_in[6];
    const float* b_ih1 = (const float*)d_in[7];
    const float* b_hh1 = (const float*)d_in[8];
    const float* fc1_w = (const float*)d_in[9];
    const float* fc1_b = (const float*)d_in[10];
    const float* fc2_w = (const float*)d_in[11];
    const float* fc2_b = (const float*)d_in[12];
    float* out = (float*)d_out;

    lstm2_inreg_kernel<<<NBLOCKS, NTHREADS>>>(
        x, w_ih0, w_hh0, b_ih0, b_hh0,
        w_ih1, w_hh1, b_ih1, b_hh1,
        fc1_w, fc1_b, fc2_w, fc2_b, out);
}

// round 8
// speedup vs baseline: 2.6130x; 1.0501x over previous
#include <cuda_runtime.h>

// Fixed shapes
#define TLEN 2048
#define HD   64
#define HS   68          // padded h-row stride
#define BPB  4
#define NTHREADS 512
#define NBLOCKS  128

// SMEM (floats): ping-pong h buffers + head scratch
//   bufA: h1@0, h2@272   bufB: h1@544, h2@816   ms@1088
#define BUF   544
#define OFF_H2 272
#define OFF_MS 1088
#define SMEM_TOT 1600

__device__ __forceinline__ float tanh_ap(float v) {
    float r;
    asm("tanh.approx.f32 %0, %1;" : "=f"(r) : "f"(v));
    return r;
}
__device__ __forceinline__ float sigm_ap(float v) {
    return fmaf(0.5f, tanh_ap(0.5f * v), 0.5f);
}

__global__ __launch_bounds__(NTHREADS, 1)
void lstm2_rs_kernel(
    const float* __restrict__ x,      // [B, T]
    const float* __restrict__ w_ih0,  // [256, 1]
    const float* __restrict__ w_hh0,  // [256, 64]
    const float* __restrict__ b_ih0,  // [256]
    const float* __restrict__ b_hh0,  // [256]
    const float* __restrict__ w_ih1,  // [256, 64]
    const float* __restrict__ w_hh1,  // [256, 64]
    const float* __restrict__ b_ih1,  // [256]
    const float* __restrict__ b_hh1,  // [256]
    const float* __restrict__ fc1_w,  // [128, 64]
    const float* __restrict__ fc1_b,  // [128]
    const float* __restrict__ fc2_w,  // [10, 128]
    const float* __restrict__ fc2_b,  // [10]
    float* __restrict__ out)          // [B, 10]
{
    __shared__ float sm[SMEM_TOT];
    float* ms = sm + OFF_MS;

    const int tid = threadIdx.x;
    const int l   = tid & 31;
    const int q   = l >> 3;           // K-quarter AND final batch of this lane
    const bool q0 = (l >> 3) & 1;
    const bool q1 = (l >> 4) & 1;
    const int gg  = (l >> 2) & 1;     // 0: (i,g) gates + L1 pointwise; 1: (f,o) + L2
    const int uu  = l & 3;
    const int w   = tid >> 5;
    const int u   = w * 4 + uu;       // hidden unit 0..63
    const int j0  = u + gg * 128;
    const int j1  = u + 64 + gg * 128;
    const int bbase = blockIdx.x * BPB;

    // ---- Weights into registers (K interleaved: k = 16*i + 4*q + e) ----
    float wA[2][16], wCi[2][16], wCh[2][16];
    #pragma unroll
    for (int g = 0; g < 2; ++g) {
        const int jg = g ? j1 : j0;
        #pragma unroll
        for (int i = 0; i < 4; ++i)
            #pragma unroll
            for (int e = 0; e < 4; ++e) {
                const int k = 16 * i + 4 * q + e;
                wA[g][4*i+e]  = w_hh0[jg * HD + k];
                wCi[g][4*i+e] = w_ih1[jg * HD + k];
                wCh[g][4*i+e] = w_hh1[jg * HD + k];
            }
    }
    const float bA0 = b_ih0[j0] + b_hh0[j0];
    const float bA1 = b_ih0[j1] + b_hh0[j1];
    const float bE0 = b_ih1[j0] + b_hh1[j0];
    const float bE1 = b_ih1[j1] + b_hh1[j1];
    const float wx0 = w_ih0[j0];
    const float wx1 = w_ih0[j1];

    for (int i = tid; i < OFF_MS; i += NTHREADS) sm[i] = 0.0f;
    __syncthreads();

    float cst = 0.0f;     // c1 (gg=0) or c2 (gg=1) for (unit u, batch q)

    const float* xrow = x + (bbase + q) * TLEN;
    float xcur = xrow[0];

    // Pipelined: iter t computes L1 gates(t) [h1(t-1), x(t)] and L2 gates(t-1)
    // [h1(t-1), h2(t-2)]. Ping-pong: read buf(t&1), write buf(1-(t&1)).
    for (int t = 0; t <= TLEN; ++t) {
        const float* hr = sm + ((t & 1) ? BUF : 0);
        float*       hw = sm + ((t & 1) ? 0 : BUF);
        const float* h1p = hr + (q << 2);
        const float* h2p = hr + OFF_H2 + (q << 2);

        const float xq = xcur;
        if (t + 1 < TLEN) xcur = xrow[t + 1];

        // Stage-1-reduced partials per bp-group: (gate, matrix) for batch bp+q0
        float PA0[2], PA1[2], PE0[2], PE1[2];

        #pragma unroll
        for (int bp = 0; bp < 4; bp += 2) {
            float A00=0.f,A01=0.f,A10=0.f,A11=0.f;   // L1: gate{0,1} x batch{bp,bp+1}
            float E00=0.f,E01=0.f,E10=0.f,E11=0.f;   // L2
            #pragma unroll
            for (int i = 0; i < 4; ++i) {
                const int o = i << 4;
                const float4 u0 = *(const float4*)(h1p + (bp    ) * HS + o);
                const float4 u1 = *(const float4*)(h1p + (bp + 1) * HS + o);
                A00=fmaf(wA[0][4*i+0],u0.x,A00); A00=fmaf(wA[0][4*i+1],u0.y,A00);
                A00=fmaf(wA[0][4*i+2],u0.z,A00); A00=fmaf(wA[0][4*i+3],u0.w,A00);
                A01=fmaf(wA[0][4*i+0],u1.x,A01); A01=fmaf(wA[0][4*i+1],u1.y,A01);
                A01=fmaf(wA[0][4*i+2],u1.z,A01); A01=fmaf(wA[0][4*i+3],u1.w,A01);
                A10=fmaf(wA[1][4*i+0],u0.x,A10); A10=fmaf(wA[1][4*i+1],u0.y,A10);
                A10=fmaf(wA[1][4*i+2],u0.z,A10); A10=fmaf(wA[1][4*i+3],u0.w,A10);
                A11=fmaf(wA[1][4*i+0],u1.x,A11); A11=fmaf(wA[1][4*i+1],u1.y,A11);
                A11=fmaf(wA[1][4*i+2],u1.z,A11); A11=fmaf(wA[1][4*i+3],u1.w,A11);
                E00=fmaf(wCi[0][4*i+0],u0.x,E00); E00=fmaf(wCi[0][4*i+1],u0.y,E00);
                E00=fmaf(wCi[0][4*i+2],u0.z,E00); E00=fmaf(wCi[0][4*i+3],u0.w,E00);
                E01=fmaf(wCi[0][4*i+0],u1.x,E01); E01=fmaf(wCi[0][4*i+1],u1.y,E01);
                E01=fmaf(wCi[0][4*i+2],u1.z,E01); E01=fmaf(wCi[0][4*i+3],u1.w,E01);
                E10=fmaf(wCi[1][4*i+0],u0.x,E10); E10=fmaf(wCi[1][4*i+1],u0.y,E10);
                E10=fmaf(wCi[1][4*i+2],u0.z,E10); E10=fmaf(wCi[1][4*i+3],u0.w,E10);
                E11=fmaf(wCi[1][4*i+0],u1.x,E11); E11=fmaf(wCi[1][4*i+1],u1.y,E11);
                E11=fmaf(wCi[1][4*i+2],u1.z,E11); E11=fmaf(wCi[1][4*i+3],u1.w,E11);
            }
            #pragma unroll
            for (int i = 0; i < 4; ++i) {
                const int o = i << 4;
                const float4 v0 = *(const float4*)(h2p + (bp    ) * HS + o);
                const float4 v1 = *(const float4*)(h2p + (bp + 1) * HS + o);
                E00=fmaf(wCh[0][4*i+0],v0.x,E00); E00=fmaf(wCh[0][4*i+1],v0.y,E00);
                E00=fmaf(wCh[0][4*i+2],v0.z,E00); E00=fmaf(wCh[0][4*i+3],v0.w,E00);
                E01=fmaf(wCh[0][4*i+0],v1.x,E01); E01=fmaf(wCh[0][4*i+1],v1.y,E01);
                E01=fmaf(wCh[0][4*i+2],v1.z,E01); E01=fmaf(wCh[0][4*i+3],v1.w,E01);
                E10=fmaf(wCh[1][4*i+0],v0.x,E10); E10=fmaf(wCh[1][4*i+1],v0.y,E10);
                E10=fmaf(wCh[1][4*i+2],v0.z,E10); E10=fmaf(wCh[1][4*i+3],v0.w,E10);
                E11=fmaf(wCh[1][4*i+0],v1.x,E11); E11=fmaf(wCh[1][4*i+1],v1.y,E11);
                E11=fmaf(wCh[1][4*i+2],v1.z,E11); E11=fmaf(wCh[1][4*i+3],v1.w,E11);
            }
            // Stage 1 (xor 8): combine K-quarter pairs, scatter batch by q0.
            // Lane keeps batch bp+q0, sends batch bp+(1-q0).
            const int gi = bp >> 1;
            {
                float s = q0 ? A00 : A01;
                float kv = q0 ? A01 : A00;
                PA0[gi] = kv + __shfl_xor_sync(0xffffffffu, s, 8);
            }
            {
                float s = q0 ? A10 : A11;
                float kv = q0 ? A11 : A10;
                PA1[gi] = kv + __shfl_xor_sync(0xffffffffu, s, 8);
            }
            {
                float s = q0 ? E00 : E01;
                float kv = q0 ? E01 : E00;
                PE0[gi] = kv + __shfl_xor_sync(0xffffffffu, s, 8);
            }
            {
                float s = q0 ? E10 : E11;
                float kv = q0 ? E11 : E10;
                PE1[gi] = kv + __shfl_xor_sync(0xffffffffu, s, 8);
            }
        }

        // Stage 2 (xor 16): combine K-halves, scatter batch high bit by q1.
        // Lane keeps group q1 (its batch q = 2*q1 + q0), sends the other group.
        float vA0, vA1, vE0, vE1;
        {
            float s = q1 ? PA0[0] : PA0[1];
            float kv = q1 ? PA0[1] : PA0[0];
            vA0 = kv + __shfl_xor_sync(0xffffffffu, s, 16);
        }
        {
            float s = q1 ? PA1[0] : PA1[1];
            float kv = q1 ? PA1[1] : PA1[0];
            vA1 = kv + __shfl_xor_sync(0xffffffffu, s, 16);
        }
        {
            float s = q1 ? PE0[0] : PE0[1];
            float kv = q1 ? PE0[1] : PE0[0];
            vE0 = kv + __shfl_xor_sync(0xffffffffu, s, 16);
        }
        {
            float s = q1 ? PE1[0] : PE1[1];
            float kv = q1 ? PE1[1] : PE1[0];
            vE1 = kv + __shfl_xor_sync(0xffffffffu, s, 16);
        }

        // Bias + x (batch q)
        vA0 = fmaf(wx0, xq, vA0 + bA0);
        vA1 = fmaf(wx1, xq, vA1 + bA1);
        vE0 += bE0;
        vE1 += bE1;

        // Gate assembly via pair exchange (l <-> l^4)
        const float t0 = gg ? vA0 : vE0;
        const float t1 = gg ? vA1 : vE1;
        const float r0 = __shfl_xor_sync(0xffffffffu, t0, 4);
        const float r1 = __shfl_xor_sync(0xffffffffu, t1, 4);
        const float gi = gg ? r0 : vA0;
        const float gf = gg ? r1 : vA1;
        const float gG = gg ? vE0 : r0;
        const float gO = gg ? vE1 : r1;

        // In-register pointwise: gg=0 -> layer1 step t ; gg=1 -> layer2 step t-1
        if (gg ? (t > 0) : (t < TLEN)) {
            const float iv = sigm_ap(gi);
            const float fv = sigm_ap(gf);
            const float gv = tanh_ap(gG);
            const float ov = sigm_ap(gO);
            cst = fmaf(fv, cst, iv * gv);
            hw[gg * OFF_H2 + q * HS + u] = ov * tanh_ap(cst);
        }
        __syncthreads();
    }

    // ================= Head =================
    // final h2 = h2(TLEN-1), written at iter TLEN into bufB
    const float* h2f = sm + BUF + OFF_H2;
    {   // fc1: one (batch, out) per thread — 4*128 = 512
        int b = tid >> 7;
        int n = tid & 127;
        float acc = fc1_b[n];
        const float* wr = &fc1_w[n * HD];
        const float* hr = h2f + b * HS;
        #pragma unroll
        for (int d = 0; d < HD; ++d) acc = fmaf(wr[d], hr[d], acc);
        ms[tid] = fmaxf(acc, 0.0f);
    }
    __syncthreads();
    if (tid < BPB * 10) {
        int b = tid / 10;
        int n = tid - b * 10;
        float acc = fc2_b[n];
        const float* wr = &fc2_w[n * 128];
        const float* mr = &ms[b * 128];
        #pragma unroll
        for (int k = 0; k < 128; ++k) acc = fmaf(wr[k], mr[k], acc);
        out[(bbase + b) * 10 + n] = acc;
    }
}

extern "C" void kernel_launch(void* const* d_in, const int* in_sizes, int n_in,
                              void* d_out, int out_size)
{
    const float* x     = (const float*)d_in[0];
    const float* w_ih0 = (const float*)d_in[1];
    const float* w_hh0 = (const float*)d_in[2];
    const float* b_ih0 = (const float*)d_in[3];
    const float* b_hh0 = (const float*)d_in[4];
    const float* w_ih1 = (const float*)d_in[5];
    const float* w_hh1 = (const float*)d_in[6];
    const float* b_ih1 = (const float*)d_in[7];
    const float* b_hh1 = (const float*)d_in[8];
    const float* fc1_w = (const float*)d_in[9];
    const float* fc1_b = (const float*)d_in[10];
    const float* fc2_w = (const float*)d_in[11];
    const float* fc2_b = (const float*)d_in[12];
    float* out = (float*)d_out;

    lstm2_rs_kernel<<<NBLOCKS, NTHREADS>>>(
        x, w_ih0, w_hh0, b_ih0, b_hh0,
        w_ih1, w_hh1, b_ih1, b_hh1,
        fc1_w, fc1_b, fc2_w, fc2_b, out);
}